// round 14
// baseline (speedup 1.0000x reference)
#include <cuda_runtime.h>
#include <cuda_bf16.h>

#define FRAME_L   1024
#define HOP       256

// ---------------------------------------------------------------------------
// Compile-time half-Hann table: g_hh.v[i] = 0.5 * (0.5 - 0.5*cos(2*pi*i/1024))
// Pre-halved: interior path needs no normalization; edge ratio acc/ws is
// invariant under joint halving. Quadrature complement on the halved table:
//   h(j+512) = 0.5 - h(j),  h(j+768) = 0.5 - h(j+256)   (to 1 ulp)
// => only k=0,1 weights are loaded; k=2,3 derived by FADD at the use site
//    (rematerialized, not stored: keeps live registers at 8, not 16).
// ---------------------------------------------------------------------------
struct alignas(16) HannTab { float v[FRAME_L]; };

constexpr double kPI = 3.141592653589793238462643383279502884;

constexpr double ccos_core(double x) {   // |x| <= pi/2, Taylor, err < 1e-16
    double x2 = x * x, s = 1.0, term = 1.0;
    for (int k = 1; k <= 10; k++) { term *= -x2 / (double)((2*k-1)*(2*k)); s += term; }
    return s;
}
constexpr double ccos(double x) {        // x in [0, 2*pi)
    if (x > kPI) x = 2.0 * kPI - x;
    if (x > 0.5 * kPI) return -ccos_core(kPI - x);
    return ccos_core(x);
}
constexpr HannTab make_half_hann() {
    HannTab t{};
    for (int i = 0; i < FRAME_L; i++) {
        double th = (2.0 * kPI * (double)i) / (double)FRAME_L;
        t.v[i] = (float)(0.5 * (0.5 - 0.5 * ccos(th)));
    }
    return t;
}
__device__ constexpr HannTab g_hh = make_half_hann();

// Gather body, compile-time (K, I). Range proofs (scale in [0.25,4] exactly):
//   * x < 0 only possible for j <= 1  -> clamp only at (k=0, i<2)
//   * x <= 1021.5 at k=0              -> no min(x0,1022) at k=0
//   * nlen >= 256 > j at k=0          -> no zeroing select at k=0
template<int K, int I>
__device__ __forceinline__ float psola_gather(const float* __restrict__ fr,
                                              float scale, float xbase, float rem)
{
    float x = fmaf((float)I, scale, xbase);
    if (K == 0 && I < 2) x = fmaxf(x, 0.0f);
    int x0 = __float2int_rd(x);
    if (K != 0) x0 = min(x0, FRAME_L - 2);
    float w = x - (float)x0;
    float a = __ldg(fr + x0);
    float b = __ldg(fr + x0 + 1);           // immediate +4B offset
    float v = fmaf(b - a, w, a);
    if (K == 0) return v;
    return ((float)I < rem) ? v : 0.0f;
}

__global__ void __launch_bounds__(256, 8)   // force 32 regs -> occ 8 blocks/SM
psola_kernel(const float* __restrict__ wav,
             const float* __restrict__ src_f0,
             const float* __restrict__ tgt_f0,
             const int*   __restrict__ voiced,
             float* __restrict__ out,
             int T, int nf)
{
    __shared__ float2 s_par[8];

    int fbase = ((int)blockIdx.x << 2) - 3;     // first frame this block can touch
    if (threadIdx.x < 8) {
        int f = fbase + (int)threadIdx.x;
        float2 p = make_float2(1.0f, (float)FRAME_L);
        if (f >= 0 && f < nf) {
            float s = src_f0[f];
            float t = tgt_f0[f];
            if ((voiced[f] != 0) && (s >= 1.0f) && (t >= 1.0f)) {
                // IEEE divide: must match jnp fp32 so rintf doesn't flip
                float ratio = fminf(fmaxf(s / t, 0.25f), 4.0f);
                float nl = fmaxf(1.0f, rintf((float)FRAME_L * ratio));
                p = make_float2((float)FRAME_L / nl, nl);
            }
        }
        s_par[threadIdx.x] = p;
    }
    __syncthreads();

    int t4 = ((int)(blockIdx.x * blockDim.x + threadIdx.x)) << 2;
    if (t4 >= T) return;

    int fmax  = t4 >> 8;          // floor(t/HOP); uniform across warp
    int jb    = t4 & 255;         // t mod HOP (multiple of 4)
    int sbase = fmax - fbase;     // smem slot for k=0 (in [3,6])

    float jhb = (float)jb + 0.5f; // exact; one I2F for the thread

    // Hann weights: load k=0,1 only; k=2,3 rematerialized at use.
    float4 h40 = *reinterpret_cast<const float4*>(g_hh.v + jb);
    float4 h41 = *reinterpret_cast<const float4*>(g_hh.v + jb + 256);
    float h0[4] = {h40.x, h40.y, h40.z, h40.w};
    float h1[4] = {h41.x, h41.y, h41.z, h41.w};

    // Per-frame derived params.
    float scale_k[4], xbase_k[4], rem_k[4];
    #pragma unroll
    for (int k = 0; k < 4; k++) {
        float2 p   = s_par[sbase - k];
        float  xk  = jhb + (float)(k << 8);     // jb + 256k + 0.5, exact
        scale_k[k] = p.x;
        xbase_k[k] = fmaf(xk, p.x, -0.5f);
        rem_k[k]   = p.y - (xk - 0.5f);         // nlen - j0, exact
    }

    float acc[4];
    bool interior = (fmax >= 3) & (fmax <= nf - 1);   // warp-uniform

    if (interior) {
        // Hot path: no ws bookkeeping (weight sum over k is exactly 1).
        const float* fr0 = wav + ((fmax - 0) << 8);
        const float* fr1 = wav + ((fmax - 1) << 8);
        const float* fr2 = wav + ((fmax - 2) << 8);
        const float* fr3 = wav + ((fmax - 3) << 8);

        #define PSOLA_SAMPLE(I)                                                   \
        {                                                                         \
            float c0 = psola_gather<0,I>(fr0, scale_k[0], xbase_k[0], rem_k[0]);  \
            float c1 = psola_gather<1,I>(fr1, scale_k[1], xbase_k[1], rem_k[1]);  \
            float c2 = psola_gather<2,I>(fr2, scale_k[2], xbase_k[2], rem_k[2]);  \
            float c3 = psola_gather<3,I>(fr3, scale_k[3], xbase_k[3], rem_k[3]);  \
            float s01 = fmaf(c0, h0[I], c1 * h1[I]);                              \
            float s23 = fmaf(c2, 0.5f - h0[I], c3 * (0.5f - h1[I]));              \
            acc[I] = s01 + s23;                                                   \
        }
        PSOLA_SAMPLE(0)
        PSOLA_SAMPLE(1)
        PSOLA_SAMPLE(2)
        PSOLA_SAMPLE(3)
        #undef PSOLA_SAMPLE

        float4 r; r.x = acc[0]; r.y = acc[1]; r.z = acc[2]; r.w = acc[3];
        *reinterpret_cast<float4*>(out + t4) = r;
    } else {
        // Edge path (tiny fraction of blocks): generic loop with ws.
        float ws[4] = {0.f, 0.f, 0.f, 0.f};
        acc[0] = acc[1] = acc[2] = acc[3] = 0.f;
        #pragma unroll
        for (int k = 0; k < 4; k++) {
            int f = fmax - k;
            if (f < 0 || f >= nf) continue;
            const float* __restrict__ fr = wav + (f << 8);
            float sc = scale_k[k], xb = xbase_k[k], rm = rem_k[k];
            #pragma unroll
            for (int i = 0; i < 4; i++) {
                float hw = (k == 0) ? h0[i]
                         : (k == 1) ? h1[i]
                         : (k == 2) ? (0.5f - h0[i])
                                    : (0.5f - h1[i]);
                ws[i] += hw;
                float x = fmaxf(fmaf((float)i, sc, xb), 0.0f);
                int x0 = min(__float2int_rd(x), FRAME_L - 2);
                float w = x - (float)x0;
                float a = __ldg(fr + x0);
                float b = __ldg(fr + x0 + 1);
                float v = fmaf(b - a, w, a);
                float c = ((float)i < rm) ? v : 0.0f;
                acc[i] = fmaf(c, hw, acc[i]);
            }
        }
        float4 r;
        r.x = (ws[0] > 1e-8f) ? acc[0] / ws[0] : acc[0];
        r.y = (ws[1] > 1e-8f) ? acc[1] / ws[1] : acc[1];
        r.z = (ws[2] > 1e-8f) ? acc[2] / ws[2] : acc[2];
        r.w = (ws[3] > 1e-8f) ? acc[3] / ws[3] : acc[3];
        *reinterpret_cast<float4*>(out + t4) = r;
    }
}

extern "C" void kernel_launch(void* const* d_in, const int* in_sizes, int n_in,
                              void* d_out, int out_size)
{
    const float* wav    = (const float*)d_in[0];
    const float* src_f0 = (const float*)d_in[1];
    const float* tgt_f0 = (const float*)d_in[2];
    const int*   voiced = (const int*)d_in[3];
    float* out = (float*)d_out;

    int T  = in_sizes[0];
    int nf_cap = (T - FRAME_L) / HOP + 1;
    int nf = in_sizes[1] < nf_cap ? in_sizes[1] : nf_cap;

    int threads = 256;
    int n4 = (T + 3) / 4;
    int blocks = (n4 + threads - 1) / threads;
    psola_kernel<<<blocks, threads>>>(wav, src_f0, tgt_f0, voiced, out, T, nf);
}

// round 15
// speedup vs baseline: 1.5360x; 1.5360x over previous
#include <cuda_runtime.h>
#include <cuda_bf16.h>

#define FRAME_L   1024
#define HOP       256

// ---------------------------------------------------------------------------
// Compile-time half-Hann table: g_hh.v[i] = 0.5 * (0.5 - 0.5*cos(2*pi*i/1024))
// Pre-halved: interior path needs no normalization; edge ratio acc/ws is
// invariant under joint halving. Quadrature complement on the halved table:
//   h(j+512) = 0.5 - h(j),  h(j+768) = 0.5 - h(j+256)   (to 1 ulp)
// => only k=0,1 weights are loaded; k=2,3 derived by FADD.
// ---------------------------------------------------------------------------
struct alignas(16) HannTab { float v[FRAME_L]; };

constexpr double kPI = 3.141592653589793238462643383279502884;

constexpr double ccos_core(double x) {   // |x| <= pi/2, Taylor, err < 1e-16
    double x2 = x * x, s = 1.0, term = 1.0;
    for (int k = 1; k <= 10; k++) { term *= -x2 / (double)((2*k-1)*(2*k)); s += term; }
    return s;
}
constexpr double ccos(double x) {        // x in [0, 2*pi)
    if (x > kPI) x = 2.0 * kPI - x;
    if (x > 0.5 * kPI) return -ccos_core(kPI - x);
    return ccos_core(x);
}
constexpr HannTab make_half_hann() {
    HannTab t{};
    for (int i = 0; i < FRAME_L; i++) {
        double th = (2.0 * kPI * (double)i) / (double)FRAME_L;
        t.v[i] = (float)(0.5 * (0.5 - 0.5 * ccos(th)));
    }
    return t;
}
__device__ constexpr HannTab g_hh = make_half_hann();

// Gather body, compile-time (K, I). Range proofs (scale in [0.25,4] exactly):
//   * x < 0 only possible for j <= 1  -> clamp only at (k=0, i<2)
//   * x <= 1021.5 at k=0              -> no min(x0,1022) at k=0
//   * nlen >= 256 > j at k=0          -> no zeroing select at k=0
template<int K, int I>
__device__ __forceinline__ float psola_gather(const float* __restrict__ fr,
                                              float scale, float xbase, float rem)
{
    float x = fmaf((float)I, scale, xbase);
    if (K == 0 && I < 2) x = fmaxf(x, 0.0f);
    int x0 = __float2int_rd(x);
    if (K != 0) x0 = min(x0, FRAME_L - 2);
    float w = x - (float)x0;
    float a = __ldg(fr + x0);
    float b = __ldg(fr + x0 + 1);           // immediate +4B offset
    float v = fmaf(b - a, w, a);
    if (K == 0) return v;
    return ((float)I < rem) ? v : 0.0f;
}

__global__ void __launch_bounds__(256, 7)   // reg budget 36: +1 block/SM vs R13, no spill cliff
psola_kernel(const float* __restrict__ wav,
             const float* __restrict__ src_f0,
             const float* __restrict__ tgt_f0,
             const int*   __restrict__ voiced,
             float* __restrict__ out,
             int T, int nf)
{
    __shared__ float2 s_par[8];

    int fbase = ((int)blockIdx.x << 2) - 3;     // first frame this block can touch
    if (threadIdx.x < 8) {
        int f = fbase + (int)threadIdx.x;
        float2 p = make_float2(1.0f, (float)FRAME_L);
        if (f >= 0 && f < nf) {
            float s = src_f0[f];
            float t = tgt_f0[f];
            if ((voiced[f] != 0) && (s >= 1.0f) && (t >= 1.0f)) {
                // IEEE divide: must match jnp fp32 so rintf doesn't flip
                float ratio = fminf(fmaxf(s / t, 0.25f), 4.0f);
                float nl = fmaxf(1.0f, rintf((float)FRAME_L * ratio));
                p = make_float2((float)FRAME_L / nl, nl);
            }
        }
        s_par[threadIdx.x] = p;
    }
    __syncthreads();

    int t4 = ((int)(blockIdx.x * blockDim.x + threadIdx.x)) << 2;
    if (t4 >= T) return;

    int fmax  = t4 >> 8;          // floor(t/HOP); uniform across warp
    int jb    = t4 & 255;         // t mod HOP (multiple of 4)
    int sbase = fmax - fbase;     // smem slot for k=0 (in [3,6])

    float jhb = (float)jb + 0.5f; // exact; one I2F for the thread

    // Hann weights: load k=0,1; derive k=2,3 by complement (table pre-halved).
    float4 h40 = *reinterpret_cast<const float4*>(g_hh.v + jb);
    float4 h41 = *reinterpret_cast<const float4*>(g_hh.v + jb + 256);
    float hh[4][4];   // hh[k][i]
    hh[0][0]=h40.x; hh[0][1]=h40.y; hh[0][2]=h40.z; hh[0][3]=h40.w;
    hh[1][0]=h41.x; hh[1][1]=h41.y; hh[1][2]=h41.z; hh[1][3]=h41.w;
    #pragma unroll
    for (int i = 0; i < 4; i++) {
        hh[2][i] = 0.5f - hh[0][i];
        hh[3][i] = 0.5f - hh[1][i];
    }

    // Per-frame derived params.
    float scale_k[4], xbase_k[4], rem_k[4];
    #pragma unroll
    for (int k = 0; k < 4; k++) {
        float2 p   = s_par[sbase - k];
        float  xk  = jhb + (float)(k << 8);     // jb + 256k + 0.5, exact
        scale_k[k] = p.x;
        xbase_k[k] = fmaf(xk, p.x, -0.5f);
        rem_k[k]   = p.y - (xk - 0.5f);         // nlen - j0, exact
    }

    float acc[4];
    bool interior = (fmax >= 3) & (fmax <= nf - 1);   // warp-uniform

    if (interior) {
        // Hot path: no ws bookkeeping (weight sum over k is exactly 1).
        const float* fr0 = wav + ((fmax - 0) << 8);
        const float* fr1 = wav + ((fmax - 1) << 8);
        const float* fr2 = wav + ((fmax - 2) << 8);
        const float* fr3 = wav + ((fmax - 3) << 8);

        #define PSOLA_SAMPLE(I)                                                   \
        {                                                                         \
            float c0 = psola_gather<0,I>(fr0, scale_k[0], xbase_k[0], rem_k[0]);  \
            float c1 = psola_gather<1,I>(fr1, scale_k[1], xbase_k[1], rem_k[1]);  \
            float c2 = psola_gather<2,I>(fr2, scale_k[2], xbase_k[2], rem_k[2]);  \
            float c3 = psola_gather<3,I>(fr3, scale_k[3], xbase_k[3], rem_k[3]);  \
            float s01 = fmaf(c0, hh[0][I], c1 * hh[1][I]);                        \
            float s23 = fmaf(c2, hh[2][I], c3 * hh[3][I]);                        \
            acc[I] = s01 + s23;                                                   \
        }
        PSOLA_SAMPLE(0)
        PSOLA_SAMPLE(1)
        PSOLA_SAMPLE(2)
        PSOLA_SAMPLE(3)
        #undef PSOLA_SAMPLE

        float4 r; r.x = acc[0]; r.y = acc[1]; r.z = acc[2]; r.w = acc[3];
        *reinterpret_cast<float4*>(out + t4) = r;
    } else {
        // Edge path (tiny fraction of blocks): generic loop with ws.
        float ws[4] = {0.f, 0.f, 0.f, 0.f};
        acc[0] = acc[1] = acc[2] = acc[3] = 0.f;
        #pragma unroll
        for (int k = 0; k < 4; k++) {
            int f = fmax - k;
            if (f < 0 || f >= nf) continue;
            const float* __restrict__ fr = wav + (f << 8);
            float sc = scale_k[k], xb = xbase_k[k], rm = rem_k[k];
            #pragma unroll
            for (int i = 0; i < 4; i++) {
                float hw = hh[k][i];
                ws[i] += hw;
                float x = fmaxf(fmaf((float)i, sc, xb), 0.0f);
                int x0 = min(__float2int_rd(x), FRAME_L - 2);
                float w = x - (float)x0;
                float a = __ldg(fr + x0);
                float b = __ldg(fr + x0 + 1);
                float v = fmaf(b - a, w, a);
                float c = ((float)i < rm) ? v : 0.0f;
                acc[i] = fmaf(c, hw, acc[i]);
            }
        }
        float4 r;
        r.x = (ws[0] > 1e-8f) ? acc[0] / ws[0] : acc[0];
        r.y = (ws[1] > 1e-8f) ? acc[1] / ws[1] : acc[1];
        r.z = (ws[2] > 1e-8f) ? acc[2] / ws[2] : acc[2];
        r.w = (ws[3] > 1e-8f) ? acc[3] / ws[3] : acc[3];
        *reinterpret_cast<float4*>(out + t4) = r;
    }
}

extern "C" void kernel_launch(void* const* d_in, const int* in_sizes, int n_in,
                              void* d_out, int out_size)
{
    const float* wav    = (const float*)d_in[0];
    const float* src_f0 = (const float*)d_in[1];
    const float* tgt_f0 = (const float*)d_in[2];
    const int*   voiced = (const int*)d_in[3];
    float* out = (float*)d_out;

    int T  = in_sizes[0];
    int nf_cap = (T - FRAME_L) / HOP + 1;
    int nf = in_sizes[1] < nf_cap ? in_sizes[1] : nf_cap;

    int threads = 256;
    int n4 = (T + 3) / 4;
    int blocks = (n4 + threads - 1) / threads;
    psola_kernel<<<blocks, threads>>>(wav, src_f0, tgt_f0, voiced, out, T, nf);
}

// round 16
// speedup vs baseline: 1.9693x; 1.2821x over previous
#include <cuda_runtime.h>
#include <cuda_bf16.h>

#define FRAME_L   1024
#define HOP       256

// ---------------------------------------------------------------------------
// Compile-time half-Hann table: g_hh.v[i] = 0.5 * (0.5 - 0.5*cos(2*pi*i/1024))
// Pre-halved: interior path needs no normalization; edge ratio acc/ws is
// invariant under joint halving. Quadrature complement on the halved table:
//   h(j+512) = 0.5 - h(j),  h(j+768) = 0.5 - h(j+256)   (to 1 ulp)
// => only k=0,1 weights are loaded; k=2,3 rematerialized (0.5f - h) at use
//    to keep live registers low. NO launch_bounds cap: ptxas caps below 40
//    quantize to 32 regs and spill (measured R14/R15).
// ---------------------------------------------------------------------------
struct alignas(16) HannTab { float v[FRAME_L]; };

constexpr double kPI = 3.141592653589793238462643383279502884;

constexpr double ccos_core(double x) {   // |x| <= pi/2, Taylor, err < 1e-16
    double x2 = x * x, s = 1.0, term = 1.0;
    for (int k = 1; k <= 10; k++) { term *= -x2 / (double)((2*k-1)*(2*k)); s += term; }
    return s;
}
constexpr double ccos(double x) {        // x in [0, 2*pi)
    if (x > kPI) x = 2.0 * kPI - x;
    if (x > 0.5 * kPI) return -ccos_core(kPI - x);
    return ccos_core(x);
}
constexpr HannTab make_half_hann() {
    HannTab t{};
    for (int i = 0; i < FRAME_L; i++) {
        double th = (2.0 * kPI * (double)i) / (double)FRAME_L;
        t.v[i] = (float)(0.5 * (0.5 - 0.5 * ccos(th)));
    }
    return t;
}
__device__ constexpr HannTab g_hh = make_half_hann();

// Gather body, compile-time (K, I). Range proofs (scale in [0.25,4] exactly):
//   * x < 0 only possible for j <= 1  -> clamp only at (k=0, i<2)
//   * x <= 1021.5 at k=0              -> no min(x0,1022) at k=0
//   * nlen >= 256 > j at k=0          -> no zeroing select at k=0 (no rem arg)
template<int K, int I>
__device__ __forceinline__ float psola_gather(const float* __restrict__ fr,
                                              float scale, float xbase, float rem = 0.0f)
{
    float x = fmaf((float)I, scale, xbase);
    if (K == 0 && I < 2) x = fmaxf(x, 0.0f);
    int x0 = __float2int_rd(x);
    if (K != 0) x0 = min(x0, FRAME_L - 2);
    float w = x - (float)x0;
    float a = __ldg(fr + x0);
    float b = __ldg(fr + x0 + 1);           // immediate +4B offset
    float v = fmaf(b - a, w, a);
    if (K == 0) return v;
    return ((float)I < rem) ? v : 0.0f;
}

__global__ void __launch_bounds__(256)
psola_kernel(const float* __restrict__ wav,
             const float* __restrict__ src_f0,
             const float* __restrict__ tgt_f0,
             const int*   __restrict__ voiced,
             float* __restrict__ out,
             int T, int nf)
{
    __shared__ float2 s_par[8];

    int fbase = ((int)blockIdx.x << 2) - 3;     // first frame this block can touch
    if (threadIdx.x < 8) {
        int f = fbase + (int)threadIdx.x;
        float2 p = make_float2(1.0f, (float)FRAME_L);
        if (f >= 0 && f < nf) {
            float s = src_f0[f];
            float t = tgt_f0[f];
            if ((voiced[f] != 0) && (s >= 1.0f) && (t >= 1.0f)) {
                // IEEE divide: must match jnp fp32 so rintf doesn't flip
                float ratio = fminf(fmaxf(s / t, 0.25f), 4.0f);
                float nl = fmaxf(1.0f, rintf((float)FRAME_L * ratio));
                p = make_float2((float)FRAME_L / nl, nl);
            }
        }
        s_par[threadIdx.x] = p;
    }
    __syncthreads();

    int t4 = ((int)(blockIdx.x * blockDim.x + threadIdx.x)) << 2;
    if (t4 >= T) return;

    int fmax  = t4 >> 8;          // floor(t/HOP); uniform across warp
    int jb    = t4 & 255;         // t mod HOP (multiple of 4)
    int sbase = fmax - fbase;     // smem slot for k=0 (in [3,6])

    float jhb = (float)jb + 0.5f; // exact; one I2F for the thread

    // Hann weights: load k=0,1 only; k=2,3 rematerialized at use.
    float4 h40 = *reinterpret_cast<const float4*>(g_hh.v + jb);
    float4 h41 = *reinterpret_cast<const float4*>(g_hh.v + jb + 256);
    float h0[4] = {h40.x, h40.y, h40.z, h40.w};
    float h1[4] = {h41.x, h41.y, h41.z, h41.w};

    // Per-frame derived params (rem for k=1..3 only).
    float scale_k[4], xbase_k[4], rem_k[4];
    #pragma unroll
    for (int k = 0; k < 4; k++) {
        float2 p   = s_par[sbase - k];
        float  xk  = jhb + (float)(k << 8);     // jb + 256k + 0.5, exact
        scale_k[k] = p.x;
        xbase_k[k] = fmaf(xk, p.x, -0.5f);
        rem_k[k]   = p.y - (xk - 0.5f);         // nlen - j0, exact
    }

    float acc[4];
    bool interior = (fmax >= 3) & (fmax <= nf - 1);   // warp-uniform

    if (interior) {
        // Hot path: no ws bookkeeping (weight sum over k is exactly 1).
        const float* fr0 = wav + ((fmax - 0) << 8);
        const float* fr1 = wav + ((fmax - 1) << 8);
        const float* fr2 = wav + ((fmax - 2) << 8);
        const float* fr3 = wav + ((fmax - 3) << 8);

        #define PSOLA_SAMPLE(I)                                                   \
        {                                                                         \
            float c0 = psola_gather<0,I>(fr0, scale_k[0], xbase_k[0]);            \
            float c1 = psola_gather<1,I>(fr1, scale_k[1], xbase_k[1], rem_k[1]);  \
            float c2 = psola_gather<2,I>(fr2, scale_k[2], xbase_k[2], rem_k[2]);  \
            float c3 = psola_gather<3,I>(fr3, scale_k[3], xbase_k[3], rem_k[3]);  \
            float s01 = fmaf(c0, h0[I], c1 * h1[I]);                              \
            float s23 = fmaf(c2, 0.5f - h0[I], c3 * (0.5f - h1[I]));              \
            acc[I] = s01 + s23;                                                   \
        }
        PSOLA_SAMPLE(0)
        PSOLA_SAMPLE(1)
        PSOLA_SAMPLE(2)
        PSOLA_SAMPLE(3)
        #undef PSOLA_SAMPLE

        float4 r; r.x = acc[0]; r.y = acc[1]; r.z = acc[2]; r.w = acc[3];
        *reinterpret_cast<float4*>(out + t4) = r;
    } else {
        // Edge path (tiny fraction of blocks): generic loop with ws.
        float ws[4] = {0.f, 0.f, 0.f, 0.f};
        acc[0] = acc[1] = acc[2] = acc[3] = 0.f;
        #pragma unroll
        for (int k = 0; k < 4; k++) {
            int f = fmax - k;
            if (f < 0 || f >= nf) continue;
            const float* __restrict__ fr = wav + (f << 8);
            float sc = scale_k[k], xb = xbase_k[k], rm = rem_k[k];
            #pragma unroll
            for (int i = 0; i < 4; i++) {
                float hw = (k == 0) ? h0[i]
                         : (k == 1) ? h1[i]
                         : (k == 2) ? (0.5f - h0[i])
                                    : (0.5f - h1[i]);
                ws[i] += hw;
                float x = fmaxf(fmaf((float)i, sc, xb), 0.0f);
                int x0 = min(__float2int_rd(x), FRAME_L - 2);
                float w = x - (float)x0;
                float a = __ldg(fr + x0);
                float b = __ldg(fr + x0 + 1);
                float v = fmaf(b - a, w, a);
                float c = ((float)i < rm) ? v : 0.0f;
                acc[i] = fmaf(c, hw, acc[i]);
            }
        }
        float4 r;
        r.x = (ws[0] > 1e-8f) ? acc[0] / ws[0] : acc[0];
        r.y = (ws[1] > 1e-8f) ? acc[1] / ws[1] : acc[1];
        r.z = (ws[2] > 1e-8f) ? acc[2] / ws[2] : acc[2];
        r.w = (ws[3] > 1e-8f) ? acc[3] / ws[3] : acc[3];
        *reinterpret_cast<float4*>(out + t4) = r;
    }
}

extern "C" void kernel_launch(void* const* d_in, const int* in_sizes, int n_in,
                              void* d_out, int out_size)
{
    const float* wav    = (const float*)d_in[0];
    const float* src_f0 = (const float*)d_in[1];
    const float* tgt_f0 = (const float*)d_in[2];
    const int*   voiced = (const int*)d_in[3];
    float* out = (float*)d_out;

    int T  = in_sizes[0];
    int nf_cap = (T - FRAME_L) / HOP + 1;
    int nf = in_sizes[1] < nf_cap ? in_sizes[1] : nf_cap;

    int threads = 256;
    int n4 = (T + 3) / 4;
    int blocks = (n4 + threads - 1) / threads;
    psola_kernel<<<blocks, threads>>>(wav, src_f0, tgt_f0, voiced, out, T, nf);
}